// round 13
// baseline (speedup 1.0000x reference)
#include <cuda_runtime.h>
#include <cuda_bf16.h>
#include <cstdint>

#define NN 50000
#define EE 800000
#define LDBIG 1312   // 4*256 (W) + 256 (skip) + 16 (ES) + 16 (ED)
#define LD2   24

// ---------------- static device scratch ----------------
__device__ __nv_bfloat16 g_XAh[(size_t)NN * 256];
__device__ __nv_bfloat16 g_XAl[(size_t)NN * 256];
__device__ float g_XB[(size_t)NN * 256];
__device__ float g_HB[(size_t)NN * LDBIG];
__device__ __nv_bfloat16 g_Wph[(size_t)LDBIG * 256];   // transposed [N][K]
__device__ __nv_bfloat16 g_Wpl[(size_t)LDBIG * 256];
__device__ float g_ESED[(size_t)NN * 32];
__device__ float g_LE[(size_t)EE * 4];
__device__ float g_WW[(size_t)EE * 4];
__device__ float g_RD[(size_t)NN * 16];
__device__ float g_sum[768], g_sumsq[768];             // per-layer regions, zeroed by cleanup
__device__ int   g_deg4[4 * NN], g_off4[4 * NN + 1], g_cnt4[4 * NN];
__device__ int   g_ssrc[EE], g_sdst[EE];
__device__ unsigned char g_scls[EE];
__device__ int   g_bsum[256], g_bpre[256];

// ---------------- BN ----------------
__global__ void colstats_kernel(const float* __restrict__ x, float* __restrict__ sum,
                                float* __restrict__ sumsq, int n, int din) {
    int t = threadIdx.x;
    int nc4 = din >> 2;
    int c4 = t % nc4;
    int rpb = blockDim.x / nc4;
    int r0 = blockIdx.x * rpb + t / nc4;
    int rstride = gridDim.x * rpb;
    float4 s = make_float4(0.f, 0.f, 0.f, 0.f);
    float4 q = make_float4(0.f, 0.f, 0.f, 0.f);
    for (int r = r0; r < n; r += rstride) {
        float4 v = *(const float4*)&x[(size_t)r * din + c4 * 4];
        s.x += v.x; s.y += v.y; s.z += v.z; s.w += v.w;
        q.x += v.x * v.x; q.y += v.y * v.y; q.z += v.z * v.z; q.w += v.w * v.w;
    }
    atomicAdd(&sum[c4 * 4 + 0], s.x); atomicAdd(&sum[c4 * 4 + 1], s.y);
    atomicAdd(&sum[c4 * 4 + 2], s.z); atomicAdd(&sum[c4 * 4 + 3], s.w);
    atomicAdd(&sumsq[c4 * 4 + 0], q.x); atomicAdd(&sumsq[c4 * 4 + 1], q.y);
    atomicAdd(&sumsq[c4 * 4 + 2], q.z); atomicAdd(&sumsq[c4 * 4 + 3], q.w);
}

// fused finalize+normalize: 16 rows per thread, 1 rsqrt per thread
__global__ void normalize_fused_kernel(const float* __restrict__ x,
                                       __nv_bfloat16* __restrict__ xh, __nv_bfloat16* __restrict__ xl,
                                       const float* __restrict__ sum, const float* __restrict__ sumsq,
                                       const float* __restrict__ g, const float* __restrict__ b,
                                       int n, int din, int ldin, float inv_n) {
    int t = threadIdx.x;
    int c = t & (din - 1);
    int rloc = t >> ldin;
    int rpb = 256 >> ldin;
    int row0 = blockIdx.x * rpb * 16 + rloc;
    float m = sum[c] * inv_n;
    float v = sumsq[c] * inv_n - m * m;
    v = v > 0.f ? v : 0.f;
    float rs = rsqrtf(v + 1e-5f);
    float gg = g[c] * rs;
    float bb = b[c] - m * gg;
#pragma unroll
    for (int it = 0; it < 16; it++) {
        int r = row0 + it * rpb;
        if (r >= n) break;
        size_t i = (size_t)r * din + c;
        float val = fmaf(x[i], gg, bb);
        __nv_bfloat16 hi = __float2bfloat16(val);
        xh[i] = hi;
        xl[i] = __float2bfloat16(val - __bfloat162float(hi));
    }
}

__global__ void cleanup_kernel(float* sum, float* sumsq) {
    int t = blockIdx.x * blockDim.x + threadIdx.x;
    if (t < 768) { sum[t] = 0.f; sumsq[t] = 0.f; }
}

// ---------------- weight packing (transposed: Wp[col][k]) ----------------
__global__ void pack_kernel(const float* __restrict__ W, const float* __restrict__ skW,
                            const float* __restrict__ As, const float* __restrict__ Ad,
                            __nv_bfloat16* __restrict__ Wph, __nv_bfloat16* __restrict__ Wpl,
                            int din, int H, int DOUT, int F, int LD) {
    int idx = blockIdx.x * blockDim.x + threadIdx.x;
    if (idx >= din * LD) return;
    int col = idx / din;
    int i = idx % din;
    float v = 0.f;
    if (col < 4 * F) {
        int j = col / F, f = col % F;
        v = W[((size_t)j * din + i) * F + f];
    } else if (col < 5 * F) {
        v = skW[(size_t)i * F + (col - 4 * F)];
    } else if (col < 5 * F + 8 * H) {
        int rem = col - 5 * F;
        const float* Amat = (rem < 4 * H) ? As : Ad;
        rem = rem % (4 * H);
        int j = rem / H, h = rem % H;
        float s = 0.f;
        for (int d = 0; d < DOUT; d++)
            s += W[((size_t)j * din + i) * F + h * DOUT + d] * Amat[((size_t)j * H + h) * DOUT + d];
        v = s;
    }
    __nv_bfloat16 hi = __float2bfloat16(v);
    Wph[idx] = hi;
    Wpl[idx] = __float2bfloat16(v - __bfloat162float(hi));
}

// ---------------- 3xBF16 split GEMM, ldmatrix + cp.async 3-stage pipeline ----------------
__device__ __forceinline__ void mma_bf16(float c[4],
                                         uint32_t a0, uint32_t a1, uint32_t a2, uint32_t a3,
                                         uint32_t b0, uint32_t b1) {
    asm volatile(
        "mma.sync.aligned.m16n8k16.row.col.f32.bf16.bf16.f32 "
        "{%0,%1,%2,%3}, {%4,%5,%6,%7}, {%8,%9}, {%0,%1,%2,%3};"
        : "+f"(c[0]), "+f"(c[1]), "+f"(c[2]), "+f"(c[3])
        : "r"(a0), "r"(a1), "r"(a2), "r"(a3), "r"(b0), "r"(b1));
}

__device__ __forceinline__ void ldsm4(uint32_t r[4], uint32_t addr) {
    asm volatile("ldmatrix.sync.aligned.m8n8.x4.shared.b16 {%0,%1,%2,%3}, [%4];"
                 : "=r"(r[0]), "=r"(r[1]), "=r"(r[2]), "=r"(r[3]) : "r"(addr));
}

__device__ __forceinline__ void cp16(uint32_t dst, const void* src, int pred_bytes) {
    asm volatile("cp.async.cg.shared.global [%0], [%1], 16, %2;"
                 :: "r"(dst), "l"(src), "r"(pred_bytes));
}

#define GBM 128
#define GBN 64
#define ASTR 80             // bytes/row (64 data + 16 pad)
#define APL (GBM * ASTR)    // 10240
#define BPL (GBN * ASTR)    // 5120
#define STG (2 * APL + 2 * BPL)   // 30720 bytes per stage
#define NSTAGE 3

extern __shared__ char sm_dyn[];

__global__ __launch_bounds__(256, 2)
void gemm_bf3_ld_kernel(const __nv_bfloat16* __restrict__ Ah, const __nv_bfloat16* __restrict__ Al,
                        const __nv_bfloat16* __restrict__ Bh, const __nv_bfloat16* __restrict__ Bl,
                        float* __restrict__ C, int M, int Nc, int K) {
    int tid = threadIdx.x;
    int wid = tid >> 5, lane = tid & 31;
    int wm = wid & 1, wn = wid >> 1;          // 2 x 4 warps; warp tile 64(m) x 16(n)
    int lr = lane >> 2, lc = lane & 3;
    int row0 = blockIdx.y * GBM, col0 = blockIdx.x * GBN;
    uint32_t sbase = (uint32_t)__cvta_generic_to_shared(sm_dyn);

    float acc[4][2][4];
#pragma unroll
    for (int mt = 0; mt < 4; mt++)
#pragma unroll
        for (int nt = 0; nt < 2; nt++)
#pragma unroll
            for (int i = 0; i < 4; i++) acc[mt][nt][i] = 0.f;

    const char* Ahc = (const char*)Ah;
    const char* Alc = (const char*)Al;
    const char* Bhc = (const char*)Bh;
    const char* Blc = (const char*)Bl;
    size_t rowB = (size_t)K * 2;   // bytes per gmem row

    int ns = K >> 5;

    int ar0 = tid >> 2, ac = tid & 3;
    int br = tid >> 2, bc = tid & 3;

#define ISSUE(s)                                                                  \
    {                                                                             \
        uint32_t base = sbase + ((s) % NSTAGE) * STG;                             \
        size_t kb = (size_t)(s) * 64;                                             \
        _Pragma("unroll")                                                         \
        for (int rep = 0; rep < 2; rep++) {                                       \
            int r = ar0 + rep * 64;                                               \
            uint32_t dst = base + r * ASTR + ac * 16;                             \
            int p = (row0 + r < M) ? 16 : 0;                                      \
            size_t off = (size_t)(row0 + r) * rowB + kb + ac * 16;                \
            cp16(dst, Ahc + off, p);                                              \
            cp16(dst + APL, Alc + off, p);                                        \
        }                                                                         \
        {                                                                         \
            uint32_t dst = base + 2 * APL + br * ASTR + bc * 16;                  \
            int p = (col0 + br < Nc) ? 16 : 0;                                    \
            size_t off = (size_t)(col0 + br) * rowB + kb + bc * 16;               \
            cp16(dst, Bhc + off, p);                                              \
            cp16(dst + BPL, Blc + off, p);                                        \
        }                                                                         \
        asm volatile("cp.async.commit_group;");                                   \
    }

    ISSUE(0);
    if (ns > 1) ISSUE(1);

    uint32_t aAddr0 = (wm * 64 + (lane & 15)) * ASTR + ((lane >> 4) << 4);
    uint32_t bAddr0 = 2 * APL + (wn * 16 + ((lane >> 4) << 3) + (lane & 7)) * ASTR
                    + (((lane >> 3) & 1) << 4);

    for (int s = 0; s < ns; s++) {
        if (s + 1 < ns) {
            asm volatile("cp.async.wait_group 1;");
        } else {
            asm volatile("cp.async.wait_group 0;");
        }
        __syncthreads();
        if (s + 2 < ns) ISSUE(s + 2);

        uint32_t base = sbase + (s % NSTAGE) * STG;
#pragma unroll
        for (int step = 0; step < 2; step++) {
            uint32_t bh[4], bl[4];
            ldsm4(bh, base + bAddr0 + step * 32);
            ldsm4(bl, base + bAddr0 + BPL + step * 32);
#pragma unroll
            for (int mt = 0; mt < 4; mt++) {
                uint32_t ah[4], al[4];
                uint32_t aa = base + aAddr0 + mt * 16 * ASTR + step * 32;
                ldsm4(ah, aa);
                ldsm4(al, aa + APL);
                mma_bf16(acc[mt][0], ah[0], ah[1], ah[2], ah[3], bl[0], bl[1]);
                mma_bf16(acc[mt][0], al[0], al[1], al[2], al[3], bh[0], bh[1]);
                mma_bf16(acc[mt][0], ah[0], ah[1], ah[2], ah[3], bh[0], bh[1]);
                mma_bf16(acc[mt][1], ah[0], ah[1], ah[2], ah[3], bl[2], bl[3]);
                mma_bf16(acc[mt][1], al[0], al[1], al[2], al[3], bh[2], bh[3]);
                mma_bf16(acc[mt][1], ah[0], ah[1], ah[2], ah[3], bh[2], bh[3]);
            }
        }
    }

#pragma unroll
    for (int mt = 0; mt < 4; mt++) {
        int rb = row0 + wm * 64 + mt * 16 + lr;
#pragma unroll
        for (int nt = 0; nt < 2; nt++) {
            int cb = col0 + wn * 16 + nt * 8 + lc * 2;
            if (rb < M && cb < Nc) {
                C[(size_t)rb * Nc + cb]     = acc[mt][nt][0];
                C[(size_t)rb * Nc + cb + 1] = acc[mt][nt][1];
            }
            if (rb + 8 < M && cb < Nc) {
                C[(size_t)(rb + 8) * Nc + cb]     = acc[mt][nt][2];
                C[(size_t)(rb + 8) * Nc + cb + 1] = acc[mt][nt][3];
            }
        }
    }
#undef ISSUE
}

// ---------------- CSR build: class-segmented (off4[node*4+c]) ----------------
__global__ void hist4_kernel(const int* __restrict__ eidx, const int* __restrict__ eattr,
                             int* __restrict__ deg4, int E, int n) {
    int e = blockIdx.x * blockDim.x + threadIdx.x;
    if (e >= E) return;
    int d = eidx[E + e];
    int c = eattr[e];
    c = (c >= 0 && c <= 3) ? c : 3;
    if ((unsigned)d < (unsigned)n) atomicAdd(&deg4[d * 4 + c], 1);
}

__global__ void scan1_kernel(const int* __restrict__ deg, int* __restrict__ off,
                             int* __restrict__ bsum, int n) {
    __shared__ int sm[1024];
    int t = threadIdx.x;
    int idx = blockIdx.x * 1024 + t;
    int v = (idx < n) ? deg[idx] : 0;
    sm[t] = v;
    __syncthreads();
    for (int d = 1; d < 1024; d <<= 1) {
        int add = (t >= d) ? sm[t - d] : 0;
        __syncthreads();
        sm[t] += add;
        __syncthreads();
    }
    if (idx < n) off[idx + 1] = sm[t];
    if (t == 1023) bsum[blockIdx.x] = sm[1023];
}

__global__ void scan2_kernel(const int* __restrict__ bsum, int* __restrict__ bpre,
                             int* __restrict__ off, int nb) {
    if (threadIdx.x == 0) {
        int run = 0;
        for (int b = 0; b < nb; b++) { bpre[b] = run; run += bsum[b]; }
        off[0] = 0;
    }
}

__global__ void scan3_kernel(int* __restrict__ off, const int* __restrict__ bpre, int n) {
    int idx = blockIdx.x * blockDim.x + threadIdx.x;
    if (idx < n) off[idx + 1] += bpre[idx >> 10];
}

__global__ void fill4_kernel(const int* __restrict__ eidx, const int* __restrict__ eattr,
                             const int* __restrict__ off4, int* __restrict__ cnt4,
                             int* __restrict__ ssrc, int* __restrict__ sdst,
                             unsigned char* __restrict__ scls, int E, int n) {
    int e = blockIdx.x * blockDim.x + threadIdx.x;
    if (e >= E) return;
    int s = eidx[e];
    int d = eidx[E + e];
    int c = eattr[e];
    c = (c >= 0 && c <= 3) ? c : 3;
    if ((unsigned)d >= (unsigned)n) return;
    int pos = off4[d * 4 + c] + atomicAdd(&cnt4[d * 4 + c], 1);
    ssrc[pos] = s;
    sdst[pos] = d;
    scls[pos] = (unsigned char)c;
}

// ---------------- message pass (layers 0,1: F=256, H=4) ----------------
__global__ void copy_esed_kernel(const float* __restrict__ HB, float* __restrict__ ESED, int n) {
    int idx = blockIdx.x * blockDim.x + threadIdx.x;
    if (idx >= n * 32) return;
    int node = idx >> 5, c = idx & 31;
    ESED[idx] = HB[(size_t)node * LDBIG + 1280 + c];
}

__global__ void edge_logit_kernel(const float* __restrict__ ESED, const int* __restrict__ ssrc,
                                  const int* __restrict__ sdst, const unsigned char* __restrict__ scls,
                                  float* __restrict__ LE, int E) {
    int i = blockIdx.x * blockDim.x + threadIdx.x;
    if (i >= E) return;
    int s = ssrc[i], d = sdst[i], c = scls[i];
    float4 es = *(const float4*)&ESED[(size_t)s * 32 + c * 4];
    float4 ed = *(const float4*)&ESED[(size_t)d * 32 + 16 + c * 4];
    float4 le;
    float v;
    v = es.x + ed.x; le.x = v > 0.f ? v : 0.2f * v;
    v = es.y + ed.y; le.y = v > 0.f ? v : 0.2f * v;
    v = es.z + ed.z; le.z = v > 0.f ? v : 0.2f * v;
    v = es.w + ed.w; le.w = v > 0.f ? v : 0.2f * v;
    *(float4*)&LE[(size_t)i * 4] = le;
}

__global__ void softmax_kernel(const float* __restrict__ LE, const int* __restrict__ off4,
                               float* __restrict__ WW, float* __restrict__ RD, int n) {
    int node = blockIdx.x * 16 + (threadIdx.x >> 4);
    if (node >= n) return;
    int sub = threadIdx.x & 15;
    int c = sub >> 2, h = sub & 3;
    int i0 = off4[node * 4 + c], i1 = off4[node * 4 + c + 1];
    float m = -3e38f;
    for (int i = i0; i < i1; i++)
        m = fmaxf(m, LE[(size_t)i * 4 + h]);
    float s = 0.f;
    for (int i = i0; i < i1; i++) {
        float p = __expf(LE[(size_t)i * 4 + h] - m);
        s += p;
        WW[(size_t)i * 4 + h] = p;
    }
    RD[node * 16 + sub] = (s > 0.f) ? (1.f / s) : 0.f;
}

// gather: single fused edge loop over all 4 class segments, batches of 8 clamped loads (MLP~8)
__global__ __launch_bounds__(256)
void gather_kernel(const float* __restrict__ HB, const int* __restrict__ off4,
                   const int* __restrict__ ssrc,
                   const float* __restrict__ WW, const float* __restrict__ RD,
                   const float* __restrict__ skb, const float* __restrict__ cb,
                   float* __restrict__ xout, int n) {
    int node = blockIdx.x;
    int f = threadIdx.x;
    int h = f >> 6;

    int o0 = __ldg(&off4[node * 4 + 0]);
    int o1 = __ldg(&off4[node * 4 + 1]);
    int o2 = __ldg(&off4[node * 4 + 2]);
    int o3 = __ldg(&off4[node * 4 + 3]);
    int o4 = __ldg(&off4[node * 4 + 4]);

    float rd0 = __ldg(&RD[node * 16 + 0 * 4 + h]);
    float rd1 = __ldg(&RD[node * 16 + 1 * 4 + h]);
    float rd2 = __ldg(&RD[node * 16 + 2 * 4 + h]);
    float rd3 = __ldg(&RD[node * 16 + 3 * 4 + h]);

    float acc = 0.f;
    for (int i = o0; i < o4; i += 8) {
        int   sj[8];
        float wj[8];
        int   co[8];
#pragma unroll
        for (int k = 0; k < 8; k++) {
            int idx = i + k;
            bool valid = idx < o4;
            int j = valid ? idx : o0;               // clamp: o0 is a valid slot when loop runs
            int cc = (idx >= o1) + (idx >= o2) + (idx >= o3);
            cc = cc > 3 ? 3 : cc;
            sj[k] = __ldg(&ssrc[j]);
            float rdc = (cc == 0) ? rd0 : (cc == 1) ? rd1 : (cc == 2) ? rd2 : rd3;
            wj[k] = valid ? (__ldg(&WW[(size_t)j * 4 + h]) * rdc) : 0.f;
            co[k] = cc * 256 + f;
        }
        float vj[8];
#pragma unroll
        for (int k = 0; k < 8; k++)
            vj[k] = __ldg(&HB[(size_t)sj[k] * LDBIG + co[k]]);
#pragma unroll
        for (int k = 0; k < 8; k++)
            acc = fmaf(wj[k], vj[k], acc);
    }

    float out = acc + HB[(size_t)node * LDBIG + 1024 + f] + skb[f]
              + cb[f] + cb[256 + f] + cb[512 + f] + cb[768 + f];
    xout[(size_t)node * 256 + f] = fmaxf(out, 0.f);
}

// ---------------- layer-2 fused message pass (F=2, H=1), class-range version ----------------
__global__ void gat_message2_kernel(const float* __restrict__ HB, const int* __restrict__ off4,
                                    const int* __restrict__ ssrc,
                                    const float* __restrict__ skb, const float* __restrict__ cb,
                                    float* __restrict__ xout, int n) {
    int node = blockIdx.x * 128 + (threadIdx.x >> 1);
    if (node >= n) return;
    int f = threadIdx.x & 1;
    const float* hrow = HB + (size_t)node * LD2;

    float out = hrow[4 * 2 + f] + skb[f] + cb[f] + cb[2 + f] + cb[4 + f] + cb[6 + f];

#pragma unroll
    for (int c = 0; c < 4; c++) {
        float edv = hrow[5 * 2 + 4 + c];
        int i0 = off4[node * 4 + c], i1 = off4[node * 4 + c + 1];
        float m = -3e38f, s = 0.f, a = 0.f;
        for (int i = i0; i < i1; i++) {
            const float* srow = HB + (size_t)ssrc[i] * LD2;
            float logit = srow[5 * 2 + c] + edv;
            logit = logit > 0.f ? logit : 0.2f * logit;
            float hv = srow[c * 2 + f];
            float nm = fmaxf(m, logit);
            float sc = __expf(m - nm);
            float p  = __expf(logit - nm);
            s = s * sc + p;
            a = a * sc + p * hv;
            m = nm;
        }
        if (s > 0.f) out += a / s;
    }
    xout[(size_t)node * 2 + f] = fmaxf(out, 0.f);
}

// ---------------- launch ----------------
extern "C" void kernel_launch(void* const* d_in, const int* in_sizes, int n_in,
                              void* d_out, int out_size) {
    __nv_bfloat16 *XAh, *XAl, *Wph, *Wpl;
    float *XB, *HB, *ESED, *LE, *WW, *RD;
    float *sum, *sumsq;
    int *deg4, *off4, *cnt4, *ssrc, *sdst, *bsum, *bpre;
    unsigned char* scls;
    cudaGetSymbolAddress((void**)&XAh, g_XAh);
    cudaGetSymbolAddress((void**)&XAl, g_XAl);
    cudaGetSymbolAddress((void**)&XB, g_XB);
    cudaGetSymbolAddress((void**)&HB, g_HB);
    cudaGetSymbolAddress((void**)&Wph, g_Wph);
    cudaGetSymbolAddress((void**)&Wpl, g_Wpl);
    cudaGetSymbolAddress((void**)&ESED, g_ESED);
    cudaGetSymbolAddress((void**)&LE, g_LE);
    cudaGetSymbolAddress((void**)&WW, g_WW);
    cudaGetSymbolAddress((void**)&RD, g_RD);
    cudaGetSymbolAddress((void**)&sum, g_sum);
    cudaGetSymbolAddress((void**)&sumsq, g_sumsq);
    cudaGetSymbolAddress((void**)&deg4, g_deg4);
    cudaGetSymbolAddress((void**)&off4, g_off4);
    cudaGetSymbolAddress((void**)&cnt4, g_cnt4);
    cudaGetSymbolAddress((void**)&ssrc, g_ssrc);
    cudaGetSymbolAddress((void**)&sdst, g_sdst);
    cudaGetSymbolAddress((void**)&scls, g_scls);
    cudaGetSymbolAddress((void**)&bsum, g_bsum);
    cudaGetSymbolAddress((void**)&bpre, g_bpre);

    cudaFuncSetAttribute(gemm_bf3_ld_kernel,
                         cudaFuncAttributeMaxDynamicSharedMemorySize, NSTAGE * STG);

    const float* x    = (const float*)d_in[0];
    const int* eidx   = (const int*)d_in[1];
    const int* eattr  = (const int*)d_in[2];
    int n = in_sizes[0] / 64;      // 50000
    int E = in_sizes[1] / 2;       // 800000
    int n4 = n * 4;

    const float* xin = x;
    for (int l = 0; l < 3; l++) {
        const float* W   = (const float*)d_in[3 + 8 * l + 0];
        const float* As  = (const float*)d_in[3 + 8 * l + 1];
        const float* Ad  = (const float*)d_in[3 + 8 * l + 2];
        const float* cb  = (const float*)d_in[3 + 8 * l + 3];
        const float* skW = (const float*)d_in[3 + 8 * l + 4];
        const float* skb = (const float*)d_in[3 + 8 * l + 5];
        const float* bng = (const float*)d_in[3 + 8 * l + 6];
        const float* bnb = (const float*)d_in[3 + 8 * l + 7];

        int din = (l == 0) ? 64 : 256;
        int ldin = (l == 0) ? 6 : 8;
        int H = (l == 2) ? 1 : 4;
        int DOUT = (l == 2) ? 2 : 64;
        int F = H * DOUT;
        int LD = (l == 2) ? LD2 : LDBIG;

        float* lsum = sum + l * 256;
        float* lsq  = sumsq + l * 256;

        pack_kernel<<<(din * LD + 255) / 256, 256>>>(W, skW, As, Ad, Wph, Wpl, din, H, DOUT, F, LD);
        colstats_kernel<<<256, 256>>>(xin, lsum, lsq, n, din);
        int rpb16 = (256 >> ldin) * 16;
        normalize_fused_kernel<<<(n + rpb16 - 1) / rpb16, 256>>>(
            xin, XAh, XAl, lsum, lsq, bng, bnb, n, din, ldin, 1.f / n);
        dim3 ggrid((LD + GBN - 1) / GBN, (n + GBM - 1) / GBM);   // col tiles fastest
        gemm_bf3_ld_kernel<<<ggrid, 256, NSTAGE * STG>>>(XAh, XAl, Wph, Wpl, HB, n, LD, din);

        if (l == 0) {
            cudaMemsetAsync(deg4, 0, n4 * sizeof(int));
            hist4_kernel<<<(E + 255) / 256, 256>>>(eidx, eattr, deg4, E, n);
            int nb = (n4 + 1023) / 1024;
            scan1_kernel<<<nb, 1024>>>(deg4, off4, bsum, n4);
            scan2_kernel<<<1, 32>>>(bsum, bpre, off4, nb);
            scan3_kernel<<<(n4 + 255) / 256, 256>>>(off4, bpre, n4);
            cudaMemsetAsync(cnt4, 0, n4 * sizeof(int));
            fill4_kernel<<<(E + 255) / 256, 256>>>(eidx, eattr, off4, cnt4, ssrc, sdst, scls, E, n);
        }

        if (l < 2) {
            copy_esed_kernel<<<(n * 32 + 255) / 256, 256>>>(HB, ESED, n);
            edge_logit_kernel<<<(E + 255) / 256, 256>>>(ESED, ssrc, sdst, scls, LE, E);
            softmax_kernel<<<(n + 15) / 16, 256>>>(LE, off4, WW, RD, n);
            gather_kernel<<<n, 256>>>(HB, off4, ssrc, WW, RD, skb, cb, XB, n);
            xin = XB;
        } else {
            gat_message2_kernel<<<(n + 127) / 128, 256>>>(HB, off4, ssrc, skb, cb, (float*)d_out, n);
        }
    }

    cleanup_kernel<<<3, 256>>>(sum, sumsq);
}

// round 17
// speedup vs baseline: 1.2191x; 1.2191x over previous
#include <cuda_runtime.h>
#include <cuda_bf16.h>
#include <cstdint>

#define NN 50000
#define EE 800000
#define LDBIG 1312   // 4*256 (W) + 256 (skip) + 16 (ES) + 16 (ED)
#define LD2   24

// ---------------- static device scratch ----------------
__device__ __nv_bfloat16 g_XAh[(size_t)NN * 256];
__device__ __nv_bfloat16 g_XAl[(size_t)NN * 256];
__device__ float g_XB[(size_t)NN * 256];
__device__ float g_HB[(size_t)NN * LDBIG];
__device__ __nv_bfloat16 g_Wph[(size_t)LDBIG * 256];   // transposed [N][K]
__device__ __nv_bfloat16 g_Wpl[(size_t)LDBIG * 256];
__device__ float g_ESED[(size_t)NN * 32];
__device__ float g_LE[(size_t)EE * 4];
__device__ float g_WW[(size_t)EE * 4];
__device__ float g_RD[(size_t)NN * 16];
__device__ float g_sum[768], g_sumsq[768];             // per-layer regions, zeroed by cleanup
__device__ int   g_deg4[4 * NN], g_off4[4 * NN + 1], g_cnt4[4 * NN];
__device__ int   g_ssrc[EE], g_sdst[EE];
__device__ unsigned char g_scls[EE];
__device__ int   g_bsum[256], g_bpre[256];

// ---------------- BN ----------------
__global__ void colstats_kernel(const float* __restrict__ x, float* __restrict__ sum,
                                float* __restrict__ sumsq, int n, int din) {
    int t = threadIdx.x;
    int nc4 = din >> 2;
    int c4 = t % nc4;
    int rpb = blockDim.x / nc4;
    int r0 = blockIdx.x * rpb + t / nc4;
    int rstride = gridDim.x * rpb;
    float4 s = make_float4(0.f, 0.f, 0.f, 0.f);
    float4 q = make_float4(0.f, 0.f, 0.f, 0.f);
    for (int r = r0; r < n; r += rstride) {
        float4 v = *(const float4*)&x[(size_t)r * din + c4 * 4];
        s.x += v.x; s.y += v.y; s.z += v.z; s.w += v.w;
        q.x += v.x * v.x; q.y += v.y * v.y; q.z += v.z * v.z; q.w += v.w * v.w;
    }
    atomicAdd(&sum[c4 * 4 + 0], s.x); atomicAdd(&sum[c4 * 4 + 1], s.y);
    atomicAdd(&sum[c4 * 4 + 2], s.z); atomicAdd(&sum[c4 * 4 + 3], s.w);
    atomicAdd(&sumsq[c4 * 4 + 0], q.x); atomicAdd(&sumsq[c4 * 4 + 1], q.y);
    atomicAdd(&sumsq[c4 * 4 + 2], q.z); atomicAdd(&sumsq[c4 * 4 + 3], q.w);
}

// fused finalize+normalize: 16 rows per thread, 1 rsqrt per thread
__global__ void normalize_fused_kernel(const float* __restrict__ x,
                                       __nv_bfloat16* __restrict__ xh, __nv_bfloat16* __restrict__ xl,
                                       const float* __restrict__ sum, const float* __restrict__ sumsq,
                                       const float* __restrict__ g, const float* __restrict__ b,
                                       int n, int din, int ldin, float inv_n) {
    int t = threadIdx.x;
    int c = t & (din - 1);
    int rloc = t >> ldin;
    int rpb = 256 >> ldin;
    int row0 = blockIdx.x * rpb * 16 + rloc;
    float m = sum[c] * inv_n;
    float v = sumsq[c] * inv_n - m * m;
    v = v > 0.f ? v : 0.f;
    float rs = rsqrtf(v + 1e-5f);
    float gg = g[c] * rs;
    float bb = b[c] - m * gg;
#pragma unroll
    for (int it = 0; it < 16; it++) {
        int r = row0 + it * rpb;
        if (r >= n) break;
        size_t i = (size_t)r * din + c;
        float val = fmaf(x[i], gg, bb);
        __nv_bfloat16 hi = __float2bfloat16(val);
        xh[i] = hi;
        xl[i] = __float2bfloat16(val - __bfloat162float(hi));
    }
}

__global__ void cleanup_kernel(float* sum, float* sumsq) {
    int t = blockIdx.x * blockDim.x + threadIdx.x;
    if (t < 768) { sum[t] = 0.f; sumsq[t] = 0.f; }
}

// ---------------- weight packing (transposed: Wp[col][k]) ----------------
__global__ void pack_kernel(const float* __restrict__ W, const float* __restrict__ skW,
                            const float* __restrict__ As, const float* __restrict__ Ad,
                            __nv_bfloat16* __restrict__ Wph, __nv_bfloat16* __restrict__ Wpl,
                            int din, int H, int DOUT, int F, int LD) {
    int idx = blockIdx.x * blockDim.x + threadIdx.x;
    if (idx >= din * LD) return;
    int col = idx / din;
    int i = idx % din;
    float v = 0.f;
    if (col < 4 * F) {
        int j = col / F, f = col % F;
        v = W[((size_t)j * din + i) * F + f];
    } else if (col < 5 * F) {
        v = skW[(size_t)i * F + (col - 4 * F)];
    } else if (col < 5 * F + 8 * H) {
        int rem = col - 5 * F;
        const float* Amat = (rem < 4 * H) ? As : Ad;
        rem = rem % (4 * H);
        int j = rem / H, h = rem % H;
        float s = 0.f;
        for (int d = 0; d < DOUT; d++)
            s += W[((size_t)j * din + i) * F + h * DOUT + d] * Amat[((size_t)j * H + h) * DOUT + d];
        v = s;
    }
    __nv_bfloat16 hi = __float2bfloat16(v);
    Wph[idx] = hi;
    Wpl[idx] = __float2bfloat16(v - __bfloat162float(hi));
}

// ---------------- 3xBF16 split GEMM, ldmatrix + cp.async 3-stage pipeline ----------------
__device__ __forceinline__ void mma_bf16(float c[4],
                                         uint32_t a0, uint32_t a1, uint32_t a2, uint32_t a3,
                                         uint32_t b0, uint32_t b1) {
    asm volatile(
        "mma.sync.aligned.m16n8k16.row.col.f32.bf16.bf16.f32 "
        "{%0,%1,%2,%3}, {%4,%5,%6,%7}, {%8,%9}, {%0,%1,%2,%3};"
        : "+f"(c[0]), "+f"(c[1]), "+f"(c[2]), "+f"(c[3])
        : "r"(a0), "r"(a1), "r"(a2), "r"(a3), "r"(b0), "r"(b1));
}

__device__ __forceinline__ void ldsm4(uint32_t r[4], uint32_t addr) {
    asm volatile("ldmatrix.sync.aligned.m8n8.x4.shared.b16 {%0,%1,%2,%3}, [%4];"
                 : "=r"(r[0]), "=r"(r[1]), "=r"(r[2]), "=r"(r[3]) : "r"(addr));
}

__device__ __forceinline__ void cp16(uint32_t dst, const void* src, int pred_bytes) {
    asm volatile("cp.async.cg.shared.global [%0], [%1], 16, %2;"
                 :: "r"(dst), "l"(src), "r"(pred_bytes));
}

#define GBM 128
#define GBN 64
#define ASTR 80             // bytes/row (64 data + 16 pad)
#define APL (GBM * ASTR)    // 10240
#define BPL (GBN * ASTR)    // 5120
#define STG (2 * APL + 2 * BPL)   // 30720 bytes per stage
#define NSTAGE 3

extern __shared__ char sm_dyn[];

__global__ __launch_bounds__(256, 2)
void gemm_bf3_ld_kernel(const __nv_bfloat16* __restrict__ Ah, const __nv_bfloat16* __restrict__ Al,
                        const __nv_bfloat16* __restrict__ Bh, const __nv_bfloat16* __restrict__ Bl,
                        float* __restrict__ C, int M, int Nc, int K) {
    int tid = threadIdx.x;
    int wid = tid >> 5, lane = tid & 31;
    int wm = wid & 1, wn = wid >> 1;          // 2 x 4 warps; warp tile 64(m) x 16(n)
    int lr = lane >> 2, lc = lane & 3;
    int row0 = blockIdx.y * GBM, col0 = blockIdx.x * GBN;
    uint32_t sbase = (uint32_t)__cvta_generic_to_shared(sm_dyn);

    float acc[4][2][4];
#pragma unroll
    for (int mt = 0; mt < 4; mt++)
#pragma unroll
        for (int nt = 0; nt < 2; nt++)
#pragma unroll
            for (int i = 0; i < 4; i++) acc[mt][nt][i] = 0.f;

    const char* Ahc = (const char*)Ah;
    const char* Alc = (const char*)Al;
    const char* Bhc = (const char*)Bh;
    const char* Blc = (const char*)Bl;
    size_t rowB = (size_t)K * 2;   // bytes per gmem row

    int ns = K >> 5;

    int ar0 = tid >> 2, ac = tid & 3;
    int br = tid >> 2, bc = tid & 3;

#define ISSUE(s)                                                                  \
    {                                                                             \
        uint32_t base = sbase + ((s) % NSTAGE) * STG;                             \
        size_t kb = (size_t)(s) * 64;                                             \
        _Pragma("unroll")                                                         \
        for (int rep = 0; rep < 2; rep++) {                                       \
            int r = ar0 + rep * 64;                                               \
            uint32_t dst = base + r * ASTR + ac * 16;                             \
            int p = (row0 + r < M) ? 16 : 0;                                      \
            size_t off = (size_t)(row0 + r) * rowB + kb + ac * 16;                \
            cp16(dst, Ahc + off, p);                                              \
            cp16(dst + APL, Alc + off, p);                                        \
        }                                                                         \
        {                                                                         \
            uint32_t dst = base + 2 * APL + br * ASTR + bc * 16;                  \
            int p = (col0 + br < Nc) ? 16 : 0;                                    \
            size_t off = (size_t)(col0 + br) * rowB + kb + bc * 16;               \
            cp16(dst, Bhc + off, p);                                              \
            cp16(dst + BPL, Blc + off, p);                                        \
        }                                                                         \
        asm volatile("cp.async.commit_group;");                                   \
    }

    ISSUE(0);
    if (ns > 1) ISSUE(1);

    uint32_t aAddr0 = (wm * 64 + (lane & 15)) * ASTR + ((lane >> 4) << 4);
    uint32_t bAddr0 = 2 * APL + (wn * 16 + ((lane >> 4) << 3) + (lane & 7)) * ASTR
                    + (((lane >> 3) & 1) << 4);

    for (int s = 0; s < ns; s++) {
        if (s + 1 < ns) {
            asm volatile("cp.async.wait_group 1;");
        } else {
            asm volatile("cp.async.wait_group 0;");
        }
        __syncthreads();
        if (s + 2 < ns) ISSUE(s + 2);

        uint32_t base = sbase + (s % NSTAGE) * STG;
#pragma unroll
        for (int step = 0; step < 2; step++) {
            uint32_t bh[4], bl[4];
            ldsm4(bh, base + bAddr0 + step * 32);
            ldsm4(bl, base + bAddr0 + BPL + step * 32);
#pragma unroll
            for (int mt = 0; mt < 4; mt++) {
                uint32_t ah[4], al[4];
                uint32_t aa = base + aAddr0 + mt * 16 * ASTR + step * 32;
                ldsm4(ah, aa);
                ldsm4(al, aa + APL);
                mma_bf16(acc[mt][0], ah[0], ah[1], ah[2], ah[3], bl[0], bl[1]);
                mma_bf16(acc[mt][0], al[0], al[1], al[2], al[3], bh[0], bh[1]);
                mma_bf16(acc[mt][0], ah[0], ah[1], ah[2], ah[3], bh[0], bh[1]);
                mma_bf16(acc[mt][1], ah[0], ah[1], ah[2], ah[3], bl[2], bl[3]);
                mma_bf16(acc[mt][1], al[0], al[1], al[2], al[3], bh[2], bh[3]);
                mma_bf16(acc[mt][1], ah[0], ah[1], ah[2], ah[3], bh[2], bh[3]);
            }
        }
    }

#pragma unroll
    for (int mt = 0; mt < 4; mt++) {
        int rb = row0 + wm * 64 + mt * 16 + lr;
#pragma unroll
        for (int nt = 0; nt < 2; nt++) {
            int cb = col0 + wn * 16 + nt * 8 + lc * 2;
            if (rb < M && cb < Nc) {
                C[(size_t)rb * Nc + cb]     = acc[mt][nt][0];
                C[(size_t)rb * Nc + cb + 1] = acc[mt][nt][1];
            }
            if (rb + 8 < M && cb < Nc) {
                C[(size_t)(rb + 8) * Nc + cb]     = acc[mt][nt][2];
                C[(size_t)(rb + 8) * Nc + cb + 1] = acc[mt][nt][3];
            }
        }
    }
#undef ISSUE
}

// ---------------- CSR build: class-segmented (off4[node*4+c]) ----------------
__global__ void hist4_kernel(const int* __restrict__ eidx, const int* __restrict__ eattr,
                             int* __restrict__ deg4, int E, int n) {
    int e = blockIdx.x * blockDim.x + threadIdx.x;
    if (e >= E) return;
    int d = eidx[E + e];
    int c = eattr[e];
    c = (c >= 0 && c <= 3) ? c : 3;
    if ((unsigned)d < (unsigned)n) atomicAdd(&deg4[d * 4 + c], 1);
}

__global__ void scan1_kernel(const int* __restrict__ deg, int* __restrict__ off,
                             int* __restrict__ bsum, int n) {
    __shared__ int sm[1024];
    int t = threadIdx.x;
    int idx = blockIdx.x * 1024 + t;
    int v = (idx < n) ? deg[idx] : 0;
    sm[t] = v;
    __syncthreads();
    for (int d = 1; d < 1024; d <<= 1) {
        int add = (t >= d) ? sm[t - d] : 0;
        __syncthreads();
        sm[t] += add;
        __syncthreads();
    }
    if (idx < n) off[idx + 1] = sm[t];
    if (t == 1023) bsum[blockIdx.x] = sm[1023];
}

__global__ void scan2_kernel(const int* __restrict__ bsum, int* __restrict__ bpre,
                             int* __restrict__ off, int nb) {
    if (threadIdx.x == 0) {
        int run = 0;
        for (int b = 0; b < nb; b++) { bpre[b] = run; run += bsum[b]; }
        off[0] = 0;
    }
}

__global__ void scan3_kernel(int* __restrict__ off, const int* __restrict__ bpre, int n) {
    int idx = blockIdx.x * blockDim.x + threadIdx.x;
    if (idx < n) off[idx + 1] += bpre[idx >> 10];
}

__global__ void fill4_kernel(const int* __restrict__ eidx, const int* __restrict__ eattr,
                             const int* __restrict__ off4, int* __restrict__ cnt4,
                             int* __restrict__ ssrc, int* __restrict__ sdst,
                             unsigned char* __restrict__ scls, int E, int n) {
    int e = blockIdx.x * blockDim.x + threadIdx.x;
    if (e >= E) return;
    int s = eidx[e];
    int d = eidx[E + e];
    int c = eattr[e];
    c = (c >= 0 && c <= 3) ? c : 3;
    if ((unsigned)d >= (unsigned)n) return;
    int pos = off4[d * 4 + c] + atomicAdd(&cnt4[d * 4 + c], 1);
    ssrc[pos] = s;
    sdst[pos] = d;
    scls[pos] = (unsigned char)c;
}

// ---------------- message pass (layers 0,1: F=256, H=4) ----------------
__global__ void copy_esed_kernel(const float* __restrict__ HB, float* __restrict__ ESED, int n) {
    int idx = blockIdx.x * blockDim.x + threadIdx.x;
    if (idx >= n * 32) return;
    int node = idx >> 5, c = idx & 31;
    ESED[idx] = HB[(size_t)node * LDBIG + 1280 + c];
}

__global__ void edge_logit_kernel(const float* __restrict__ ESED, const int* __restrict__ ssrc,
                                  const int* __restrict__ sdst, const unsigned char* __restrict__ scls,
                                  float* __restrict__ LE, int E) {
    int i = blockIdx.x * blockDim.x + threadIdx.x;
    if (i >= E) return;
    int s = ssrc[i], d = sdst[i], c = scls[i];
    float4 es = *(const float4*)&ESED[(size_t)s * 32 + c * 4];
    float4 ed = *(const float4*)&ESED[(size_t)d * 32 + 16 + c * 4];
    float4 le;
    float v;
    v = es.x + ed.x; le.x = v > 0.f ? v : 0.2f * v;
    v = es.y + ed.y; le.y = v > 0.f ? v : 0.2f * v;
    v = es.z + ed.z; le.z = v > 0.f ? v : 0.2f * v;
    v = es.w + ed.w; le.w = v > 0.f ? v : 0.2f * v;
    *(float4*)&LE[(size_t)i * 4] = le;
}

__global__ void softmax_kernel(const float* __restrict__ LE, const int* __restrict__ off4,
                               float* __restrict__ WW, float* __restrict__ RD, int n) {
    int node = blockIdx.x * 16 + (threadIdx.x >> 4);
    if (node >= n) return;
    int sub = threadIdx.x & 15;
    int c = sub >> 2, h = sub & 3;
    int i0 = off4[node * 4 + c], i1 = off4[node * 4 + c + 1];
    float m = -3e38f;
    for (int i = i0; i < i1; i++)
        m = fmaxf(m, LE[(size_t)i * 4 + h]);
    float s = 0.f;
    for (int i = i0; i < i1; i++) {
        float p = __expf(LE[(size_t)i * 4 + h] - m);
        s += p;
        WW[(size_t)i * 4 + h] = p;
    }
    RD[node * 16 + sub] = (s > 0.f) ? (1.f / s) : 0.f;
}

// gather: edge-parallel — warp w handles edges w, w+8, ... covering ALL 256 features;
// cross-warp reduction in smem. Cuts per-block serial chain from deg to ceil(deg/8).
__global__ __launch_bounds__(256)
void gather_kernel(const float* __restrict__ HB, const int* __restrict__ off4,
                   const int* __restrict__ ssrc,
                   const float* __restrict__ WW, const float* __restrict__ RD,
                   const float* __restrict__ skb, const float* __restrict__ cb,
                   float* __restrict__ xout, int n) {
    __shared__ float red[8][260];
    int node = blockIdx.x;
    int tid = threadIdx.x;
    int w = tid >> 5, lane = tid & 31;

    int o0 = __ldg(&off4[node * 4 + 0]);
    int o1 = __ldg(&off4[node * 4 + 1]);
    int o2 = __ldg(&off4[node * 4 + 2]);
    int o3 = __ldg(&off4[node * 4 + 3]);
    int o4 = __ldg(&off4[node * 4 + 4]);

    // lane covers f = lane*4..lane*4+3 (head h0 = lane>>4) and f = 128+lane*4.. (head h0+2)
    int h0 = lane >> 4;
    float rdA[4], rdB[4];
#pragma unroll
    for (int c = 0; c < 4; c++) {
        rdA[c] = __ldg(&RD[node * 16 + c * 4 + h0]);
        rdB[c] = __ldg(&RD[node * 16 + c * 4 + h0 + 2]);
    }

    float4 acc0 = make_float4(0.f, 0.f, 0.f, 0.f);
    float4 acc1 = make_float4(0.f, 0.f, 0.f, 0.f);

    for (int i = o0 + w; i < o4; i += 8) {
        int s = __ldg(&ssrc[i]);
        float4 ww = *(const float4*)&WW[(size_t)i * 4];
        int c = (i >= o1) + (i >= o2) + (i >= o3);
        float wh0 = (lane & 16) ? ww.y : ww.x;      // ww[h0]
        float wh1 = (lane & 16) ? ww.w : ww.z;      // ww[h0+2]
        float ra = (c == 0) ? rdA[0] : (c == 1) ? rdA[1] : (c == 2) ? rdA[2] : rdA[3];
        float rb = (c == 0) ? rdB[0] : (c == 1) ? rdB[1] : (c == 2) ? rdB[2] : rdB[3];
        wh0 *= ra;
        wh1 *= rb;
        const float* row = HB + (size_t)s * LDBIG + c * 256;
        float4 v0 = *(const float4*)&row[lane * 4];
        float4 v1 = *(const float4*)&row[128 + lane * 4];
        acc0.x = fmaf(wh0, v0.x, acc0.x);
        acc0.y = fmaf(wh0, v0.y, acc0.y);
        acc0.z = fmaf(wh0, v0.z, acc0.z);
        acc0.w = fmaf(wh0, v0.w, acc0.w);
        acc1.x = fmaf(wh1, v1.x, acc1.x);
        acc1.y = fmaf(wh1, v1.y, acc1.y);
        acc1.z = fmaf(wh1, v1.z, acc1.z);
        acc1.w = fmaf(wh1, v1.w, acc1.w);
    }

    *(float4*)&red[w][lane * 4]       = acc0;
    *(float4*)&red[w][128 + lane * 4] = acc1;
    __syncthreads();

    int f = tid;
    float acc = red[0][f] + red[1][f] + red[2][f] + red[3][f]
              + red[4][f] + red[5][f] + red[6][f] + red[7][f];

    float out = acc + HB[(size_t)node * LDBIG + 1024 + f] + skb[f]
              + cb[f] + cb[256 + f] + cb[512 + f] + cb[768 + f];
    xout[(size_t)node * 256 + f] = fmaxf(out, 0.f);
}

// ---------------- layer-2 fused message pass (F=2, H=1), class-range version ----------------
__global__ void gat_message2_kernel(const float* __restrict__ HB, const int* __restrict__ off4,
                                    const int* __restrict__ ssrc,
                                    const float* __restrict__ skb, const float* __restrict__ cb,
                                    float* __restrict__ xout, int n) {
    int node = blockIdx.x * 128 + (threadIdx.x >> 1);
    if (node >= n) return;
    int f = threadIdx.x & 1;
    const float* hrow = HB + (size_t)node * LD2;

    float out = hrow[4 * 2 + f] + skb[f] + cb[f] + cb[2 + f] + cb[4 + f] + cb[6 + f];

#pragma unroll
    for (int c = 0; c < 4; c++) {
        float edv = hrow[5 * 2 + 4 + c];
        int i0 = off4[node * 4 + c], i1 = off4[node * 4 + c + 1];
        float m = -3e38f, s = 0.f, a = 0.f;
        for (int i = i0; i < i1; i++) {
            const float* srow = HB + (size_t)ssrc[i] * LD2;
            float logit = srow[5 * 2 + c] + edv;
            logit = logit > 0.f ? logit : 0.2f * logit;
            float hv = srow[c * 2 + f];
            float nm = fmaxf(m, logit);
            float sc = __expf(m - nm);
            float p  = __expf(logit - nm);
            s = s * sc + p;
            a = a * sc + p * hv;
            m = nm;
        }
        if (s > 0.f) out += a / s;
    }
    xout[(size_t)node * 2 + f] = fmaxf(out, 0.f);
}

// ---------------- launch ----------------
extern "C" void kernel_launch(void* const* d_in, const int* in_sizes, int n_in,
                              void* d_out, int out_size) {
    __nv_bfloat16 *XAh, *XAl, *Wph, *Wpl;
    float *XB, *HB, *ESED, *LE, *WW, *RD;
    float *sum, *sumsq;
    int *deg4, *off4, *cnt4, *ssrc, *sdst, *bsum, *bpre;
    unsigned char* scls;
    cudaGetSymbolAddress((void**)&XAh, g_XAh);
    cudaGetSymbolAddress((void**)&XAl, g_XAl);
    cudaGetSymbolAddress((void**)&XB, g_XB);
    cudaGetSymbolAddress((void**)&HB, g_HB);
    cudaGetSymbolAddress((void**)&Wph, g_Wph);
    cudaGetSymbolAddress((void**)&Wpl, g_Wpl);
    cudaGetSymbolAddress((void**)&ESED, g_ESED);
    cudaGetSymbolAddress((void**)&LE, g_LE);
    cudaGetSymbolAddress((void**)&WW, g_WW);
    cudaGetSymbolAddress((void**)&RD, g_RD);
    cudaGetSymbolAddress((void**)&sum, g_sum);
    cudaGetSymbolAddress((void**)&sumsq, g_sumsq);
    cudaGetSymbolAddress((void**)&deg4, g_deg4);
    cudaGetSymbolAddress((void**)&off4, g_off4);
    cudaGetSymbolAddress((void**)&cnt4, g_cnt4);
    cudaGetSymbolAddress((void**)&ssrc, g_ssrc);
    cudaGetSymbolAddress((void**)&sdst, g_sdst);
    cudaGetSymbolAddress((void**)&scls, g_scls);
    cudaGetSymbolAddress((void**)&bsum, g_bsum);
    cudaGetSymbolAddress((void**)&bpre, g_bpre);

    cudaFuncSetAttribute(gemm_bf3_ld_kernel,
                         cudaFuncAttributeMaxDynamicSharedMemorySize, NSTAGE * STG);

    const float* x    = (const float*)d_in[0];
    const int* eidx   = (const int*)d_in[1];
    const int* eattr  = (const int*)d_in[2];
    int n = in_sizes[0] / 64;      // 50000
    int E = in_sizes[1] / 2;       // 800000
    int n4 = n * 4;

    const float* xin = x;
    for (int l = 0; l < 3; l++) {
        const float* W   = (const float*)d_in[3 + 8 * l + 0];
        const float* As  = (const float*)d_in[3 + 8 * l + 1];
        const float* Ad  = (const float*)d_in[3 + 8 * l + 2];
        const float* cb  = (const float*)d_in[3 + 8 * l + 3];
        const float* skW = (const float*)d_in[3 + 8 * l + 4];
        const float* skb = (const float*)d_in[3 + 8 * l + 5];
        const float* bng = (const float*)d_in[3 + 8 * l + 6];
        const float* bnb = (const float*)d_in[3 + 8 * l + 7];

        int din = (l == 0) ? 64 : 256;
        int ldin = (l == 0) ? 6 : 8;
        int H = (l == 2) ? 1 : 4;
        int DOUT = (l == 2) ? 2 : 64;
        int F = H * DOUT;
        int LD = (l == 2) ? LD2 : LDBIG;

        float* lsum = sum + l * 256;
        float* lsq  = sumsq + l * 256;

        pack_kernel<<<(din * LD + 255) / 256, 256>>>(W, skW, As, Ad, Wph, Wpl, din, H, DOUT, F, LD);
        colstats_kernel<<<256, 256>>>(xin, lsum, lsq, n, din);
        int rpb16 = (256 >> ldin) * 16;
        normalize_fused_kernel<<<(n + rpb16 - 1) / rpb16, 256>>>(
            xin, XAh, XAl, lsum, lsq, bng, bnb, n, din, ldin, 1.f / n);
        dim3 ggrid((LD + GBN - 1) / GBN, (n + GBM - 1) / GBM);   // col tiles fastest
        gemm_bf3_ld_kernel<<<ggrid, 256, NSTAGE * STG>>>(XAh, XAl, Wph, Wpl, HB, n, LD, din);

        if (l == 0) {
            cudaMemsetAsync(deg4, 0, n4 * sizeof(int));
            hist4_kernel<<<(E + 255) / 256, 256>>>(eidx, eattr, deg4, E, n);
            int nb = (n4 + 1023) / 1024;
            scan1_kernel<<<nb, 1024>>>(deg4, off4, bsum, n4);
            scan2_kernel<<<1, 32>>>(bsum, bpre, off4, nb);
            scan3_kernel<<<(n4 + 255) / 256, 256>>>(off4, bpre, n4);
            cudaMemsetAsync(cnt4, 0, n4 * sizeof(int));
            fill4_kernel<<<(E + 255) / 256, 256>>>(eidx, eattr, off4, cnt4, ssrc, sdst, scls, E, n);
        }

        if (l < 2) {
            copy_esed_kernel<<<(n * 32 + 255) / 256, 256>>>(HB, ESED, n);
            edge_logit_kernel<<<(E + 255) / 256, 256>>>(ESED, ssrc, sdst, scls, LE, E);
            softmax_kernel<<<(n + 15) / 16, 256>>>(LE, off4, WW, RD, n);
            gather_kernel<<<n, 256>>>(HB, off4, ssrc, WW, RD, skb, cb, XB, n);
            xin = XB;
        } else {
            gat_message2_kernel<<<(n + 127) / 128, 256>>>(HB, off4, ssrc, skb, cb, (float*)d_out, n);
        }
    }

    cleanup_kernel<<<3, 256>>>(sum, sumsq);
}